// round 7
// baseline (speedup 1.0000x reference)
#include <cuda_runtime.h>
#include <cuda_bf16.h>
#include <cstdint>

// Problem constants
static constexpr int IN_F   = 4096;           // K
static constexpr int OUT_F  = 4096;           // N
static constexpr int M_TOT  = 4 * 2048;       // 8192

// Scratch: x converted to bf16, dequantized weight stored [N][K] (B^T, K-contiguous)
__device__ __nv_bfloat16 g_Xb[(size_t)M_TOT * IN_F];   // 64 MB
__device__ __nv_bfloat16 g_Wb[(size_t)OUT_F * IN_F];   // 32 MB

// ---------------------------------------------------------------------------
// Kernel 1: fp32 -> bf16 convert of x (8 elements / thread, 16B stores)
// ---------------------------------------------------------------------------
__global__ void convert_x_kernel(const float* __restrict__ x) {
    size_t i = ((size_t)blockIdx.x * blockDim.x + threadIdx.x) * 8;
    float4 f0 = *reinterpret_cast<const float4*>(x + i);
    float4 f1 = *reinterpret_cast<const float4*>(x + i + 4);
    union { uint4 u; __nv_bfloat162 h[4]; } p;
    p.h[0] = __float22bfloat162_rn(make_float2(f0.x, f0.y));
    p.h[1] = __float22bfloat162_rn(make_float2(f0.z, f0.w));
    p.h[2] = __float22bfloat162_rn(make_float2(f1.x, f1.y));
    p.h[3] = __float22bfloat162_rn(make_float2(f1.z, f1.w));
    *reinterpret_cast<uint4*>(g_Xb + i) = p.u;
}

// ---------------------------------------------------------------------------
// Kernel 2: dequant int4 GPTQ weight -> bf16, layout [n][k] (K contiguous)
//   qweight[p][n] (p = k/8) packs 8 consecutive k values for column n.
//   W[k][n] = (((qw[p][n] >> 4*(k%8)) & 15) - z[g][n]) * scale[g][n], g = k/128
// One thread per qweight word -> 8 contiguous bf16 in row n of g_Wb (16B store).
// NOTE: scales are delivered as float32 by the harness (fp16 in the reference
// gets materialized as fp32 — confirmed by the error signatures of reading
// them as fp16 [err ~6e4 range-capped] vs bf16 [err ~1e21 range]).
// ---------------------------------------------------------------------------
__global__ void dequant_w_kernel(const int* __restrict__ qweight,
                                 const int* __restrict__ qzeros,
                                 const float* __restrict__ scales) {
    int idx = blockIdx.x * blockDim.x + threadIdx.x;   // 0 .. 512*4096-1
    int n = idx & (OUT_F - 1);
    int p = idx >> 12;                                 // k-word index, 0..511
    int g = p >> 4;                                    // group = (p*8)/128

    uint32_t w = ((const uint32_t*)qweight)[idx];
    uint32_t zw = ((const uint32_t*)qzeros)[g * (OUT_F / 8) + (n >> 3)];
    float z = (float)((zw >> (4 * (n & 7))) & 15);
    float s = scales[g * OUT_F + n];

    union { uint4 u; __nv_bfloat16 h[8]; } outp;
#pragma unroll
    for (int j = 0; j < 8; j++) {
        float wv = (float)((w >> (4 * j)) & 15);
        outp.h[j] = __float2bfloat16((wv - z) * s);
    }
    *reinterpret_cast<uint4*>(g_Wb + (size_t)n * IN_F + (size_t)p * 8) = outp.u;
}

// ---------------------------------------------------------------------------
// Kernel 3: bf16 TN GEMM  C[m][n] = sum_k Xb[m][k] * Wb[n][k], fp32 accum,
// result rounded through bf16 (reference computes in bf16) then stored fp32.
// Block tile 128x128x32, 256 threads (8 warps, 64x32 warp tiles),
// cp.async double-buffered smem with +16B row padding (conflict-free LDSM).
// ---------------------------------------------------------------------------
__global__ __launch_bounds__(256, 1)
void gemm_kernel(float* __restrict__ C) {
    constexpr int K   = IN_F;
    constexpr int LDS = 40;   // 32 bf16 + 8 pad (=80B row, keeps 16B alignment)

    __shared__ __align__(16) __nv_bfloat16 As[2][128 * LDS];
    __shared__ __align__(16) __nv_bfloat16 Bs[2][128 * LDS];

    const int tid  = threadIdx.x;
    const int bm   = blockIdx.y * 128;
    const int bn   = blockIdx.x * 128;
    const int lane = tid & 31;
    const int warp = tid >> 5;
    const int wm   = (warp >> 2) * 64;   // warp row offset (2 warp-rows)
    const int wn   = (warp & 3) * 32;    // warp col offset (4 warp-cols)

    // cp.async mapping: each thread fills 2x16B of A and 2x16B of B per stage
    const int lrow = tid >> 1;           // 0..127
    const int lcol = (tid & 1) * 16;     // 0 or 16 (bf16 elems)
    const __nv_bfloat16* gA = g_Xb + (size_t)(bm + lrow) * K + lcol;
    const __nv_bfloat16* gB = g_Wb + (size_t)(bn + lrow) * K + lcol;

    uint32_t sAb[2], sBb[2];
    sAb[0] = (uint32_t)__cvta_generic_to_shared(&As[0][0]);
    sAb[1] = (uint32_t)__cvta_generic_to_shared(&As[1][0]);
    sBb[0] = (uint32_t)__cvta_generic_to_shared(&Bs[0][0]);
    sBb[1] = (uint32_t)__cvta_generic_to_shared(&Bs[1][0]);
    const uint32_t soff = (uint32_t)(lrow * LDS + lcol) * 2;

    float acc[4][4][4];
#pragma unroll
    for (int i = 0; i < 4; i++)
#pragma unroll
        for (int t = 0; t < 4; t++)
#pragma unroll
            for (int e = 0; e < 4; e++) acc[i][t][e] = 0.0f;

    auto issue = [&](int st, int kt) {
        const __nv_bfloat16* ga = gA + kt * 32;
        const __nv_bfloat16* gb = gB + kt * 32;
        uint32_t a0 = sAb[st] + soff;
        uint32_t b0 = sBb[st] + soff;
        asm volatile("cp.async.cg.shared.global [%0], [%1], 16;\n" :: "r"(a0),      "l"(ga));
        asm volatile("cp.async.cg.shared.global [%0], [%1], 16;\n" :: "r"(a0 + 16), "l"(ga + 8));
        asm volatile("cp.async.cg.shared.global [%0], [%1], 16;\n" :: "r"(b0),      "l"(gb));
        asm volatile("cp.async.cg.shared.global [%0], [%1], 16;\n" :: "r"(b0 + 16), "l"(gb + 8));
    };

    constexpr int NT = K / 32;   // 128 k-tiles
    issue(0, 0);
    asm volatile("cp.async.commit_group;\n");

    const int r = lane & 15;     // ldmatrix row within 16
    const int c = lane >> 4;     // ldmatrix k-half (0/1)

    for (int kt = 0; kt < NT; kt++) {
        if (kt + 1 < NT) issue((kt + 1) & 1, kt + 1);
        asm volatile("cp.async.commit_group;\n");
        asm volatile("cp.async.wait_group 1;\n");
        __syncthreads();

        const int st = kt & 1;
#pragma unroll
        for (int ks = 0; ks < 2; ks++) {
            uint32_t a[4][4], b[2][4];
#pragma unroll
            for (int i = 0; i < 4; i++) {
                uint32_t addr = sAb[st] +
                    (uint32_t)((wm + i * 16 + r) * LDS + ks * 16 + c * 8) * 2;
                asm volatile("ldmatrix.sync.aligned.m8n8.x4.shared.b16 {%0,%1,%2,%3}, [%4];\n"
                    : "=r"(a[i][0]), "=r"(a[i][1]), "=r"(a[i][2]), "=r"(a[i][3]) : "r"(addr));
            }
#pragma unroll
            for (int j = 0; j < 2; j++) {
                uint32_t addr = sBb[st] +
                    (uint32_t)((wn + j * 16 + r) * LDS + ks * 16 + c * 8) * 2;
                asm volatile("ldmatrix.sync.aligned.m8n8.x4.shared.b16 {%0,%1,%2,%3}, [%4];\n"
                    : "=r"(b[j][0]), "=r"(b[j][1]), "=r"(b[j][2]), "=r"(b[j][3]) : "r"(addr));
            }
#pragma unroll
            for (int i = 0; i < 4; i++) {
#pragma unroll
                for (int t = 0; t < 4; t++) {
                    uint32_t bb0 = b[t >> 1][(t & 1)];
                    uint32_t bb1 = b[t >> 1][(t & 1) + 2];
                    asm volatile(
                        "mma.sync.aligned.m16n8k16.row.col.f32.bf16.bf16.f32 "
                        "{%0,%1,%2,%3}, {%4,%5,%6,%7}, {%8,%9}, {%0,%1,%2,%3};\n"
                        : "+f"(acc[i][t][0]), "+f"(acc[i][t][1]),
                          "+f"(acc[i][t][2]), "+f"(acc[i][t][3])
                        : "r"(a[i][0]), "r"(a[i][1]), "r"(a[i][2]), "r"(a[i][3]),
                          "r"(bb0), "r"(bb1));
                }
            }
        }
        __syncthreads();
    }

    // Epilogue: round through bf16 (reference result is bf16-valued), store fp32
#pragma unroll
    for (int i = 0; i < 4; i++) {
        int row0 = bm + wm + i * 16 + (lane >> 2);
#pragma unroll
        for (int t = 0; t < 4; t++) {
            int col = bn + wn + t * 8 + (lane & 3) * 2;
            float2 v0, v1;
            v0.x = __bfloat162float(__float2bfloat16(acc[i][t][0]));
            v0.y = __bfloat162float(__float2bfloat16(acc[i][t][1]));
            v1.x = __bfloat162float(__float2bfloat16(acc[i][t][2]));
            v1.y = __bfloat162float(__float2bfloat16(acc[i][t][3]));
            *reinterpret_cast<float2*>(C + (size_t)row0 * OUT_F + col)       = v0;
            *reinterpret_cast<float2*>(C + (size_t)(row0 + 8) * OUT_F + col) = v1;
        }
    }
}

// ---------------------------------------------------------------------------
// Launch: convert -> dequant -> GEMM (3 graph nodes, no allocs, no syncs)
// ---------------------------------------------------------------------------
extern "C" void kernel_launch(void* const* d_in, const int* in_sizes, int n_in,
                              void* d_out, int out_size) {
    const float* x       = (const float*)d_in[0];
    const int*   qweight = (const int*)d_in[1];
    const int*   qzeros  = (const int*)d_in[2];
    const float* scales  = (const float*)d_in[3];
    float*       out     = (float*)d_out;

    // 8192*4096 / (256 threads * 8 elems) = 16384 blocks
    convert_x_kernel<<<16384, 256>>>(x);
    // 512*4096 words / 256 threads = 8192 blocks
    dequant_w_kernel<<<8192, 256>>>(qweight, qzeros, scales);
    // (N/128, M/128) = (32, 64)
    dim3 grid(OUT_F / 128, M_TOT / 128);
    gemm_kernel<<<grid, 256>>>(out);
}

// round 9
// speedup vs baseline: 1.0708x; 1.0708x over previous
#include <cuda_runtime.h>
#include <cuda_bf16.h>
#include <cstdint>

// Problem constants
static constexpr int IN_F  = 4096;   // K
static constexpr int OUT_F = 4096;   // N
static constexpr int M_TOT = 8192;   // 4*2048

// GEMM tiling: CTA 128x256x32, 8 warps, warp tile 64x64, 5-stage cp.async ring
static constexpr int BM = 128, BN = 256, BK = 32;
static constexpr int STAGES = 5;
static constexpr int NT = IN_F / BK;                       // 128 K-stages
static constexpr int LDSE = 40;                            // 32 bf16 + 8 pad (80B row)
static constexpr int A_BYTES = BM * LDSE * 2;              // 10240
static constexpr int B_BYTES = BN * LDSE * 2;              // 20480
static constexpr int STAGE_BYTES = A_BYTES + B_BYTES;      // 30720
static constexpr int DYN_SMEM = STAGES * STAGE_BYTES;      // 153600

// Fused scratch: X-bf16 rows [0, M_TOT), W-bf16 (B^T, [n][k]) rows [M_TOT, M_TOT+OUT_F)
__device__ __nv_bfloat16 g_XW[(size_t)(M_TOT + OUT_F) * IN_F];   // 96 MB

// ---------------------------------------------------------------------------
// Kernel 1: fp32 -> bf16 convert of x (74.5% of HBM spec per ncu — done)
// ---------------------------------------------------------------------------
__global__ void convert_x_kernel(const float* __restrict__ x) {
    size_t i = ((size_t)blockIdx.x * blockDim.x + threadIdx.x) * 8;
    float4 f0 = *reinterpret_cast<const float4*>(x + i);
    float4 f1 = *reinterpret_cast<const float4*>(x + i + 4);
    union { uint4 u; __nv_bfloat162 h[4]; } p;
    p.h[0] = __float22bfloat162_rn(make_float2(f0.x, f0.y));
    p.h[1] = __float22bfloat162_rn(make_float2(f0.z, f0.w));
    p.h[2] = __float22bfloat162_rn(make_float2(f1.x, f1.y));
    p.h[3] = __float22bfloat162_rn(make_float2(f1.z, f1.w));
    *reinterpret_cast<uint4*>(g_XW + i) = p.u;
}

// ---------------------------------------------------------------------------
// Kernel 2: dequant int4 -> bf16, stored [n][k] at g_XW + M_TOT*IN_F.
// scales delivered as float32 by the harness (established R4/R5/R7).
// ---------------------------------------------------------------------------
__global__ void dequant_w_kernel(const int* __restrict__ qweight,
                                 const int* __restrict__ qzeros,
                                 const float* __restrict__ scales) {
    int idx = blockIdx.x * blockDim.x + threadIdx.x;   // 0 .. 512*4096-1
    int n = idx & (OUT_F - 1);
    int p = idx >> 12;
    int g = p >> 4;

    uint32_t w  = ((const uint32_t*)qweight)[idx];
    uint32_t zw = ((const uint32_t*)qzeros)[g * (OUT_F / 8) + (n >> 3)];
    float z = (float)((zw >> (4 * (n & 7))) & 15);
    float s = scales[g * OUT_F + n];

    union { uint4 u; __nv_bfloat16 h[8]; } outp;
#pragma unroll
    for (int j = 0; j < 8; j++) {
        float wv = (float)((w >> (4 * j)) & 15);
        outp.h[j] = __float2bfloat16((wv - z) * s);
    }
    *reinterpret_cast<uint4*>(g_XW + (size_t)(M_TOT + n) * IN_F + (size_t)p * 8) = outp.u;
}

// ---------------------------------------------------------------------------
// Kernel 3: bf16 TN GEMM, HMMA path (tcgen05 unavailable: harness targets
// compute_103, no `a` features). 128x256 CTA tile, 64x64 warp tiles,
// 5-stage cp.async pipeline (prefetch distance 4 stages hides DRAM latency).
// Result rounded through bf16 (reference computes in bf16), stored fp32.
// ---------------------------------------------------------------------------
__global__ __launch_bounds__(256, 1)
void gemm_kernel(float* __restrict__ C) {
    extern __shared__ __align__(16) char smem[];

    const int tid  = threadIdx.x;
    const int lane = tid & 31;
    const int warp = tid >> 5;
    const int bm   = blockIdx.y * BM;
    const int bn   = blockIdx.x * BN;
    const int wm   = (warp & 1) * 64;    // warp row offset
    const int wn   = (warp >> 1) * 64;   // warp col offset

    const uint32_t sbase = (uint32_t)__cvta_generic_to_shared(smem);

    // cp.async mapping: 1536 16B chunks/stage (A:512, B:1024), 6 per thread
    uint32_t s_off[6];
    size_t   g_off[6];
#pragma unroll
    for (int j = 0; j < 6; j++) {
        int c    = tid + 256 * j;
        bool isA = c < 512;
        int cc   = isA ? c : c - 512;
        int row  = cc >> 2, c16 = cc & 3;
        s_off[j] = (isA ? 0u : (uint32_t)A_BYTES) + (uint32_t)(row * LDSE + c16 * 8) * 2;
        g_off[j] = (size_t)(isA ? (bm + row) : (M_TOT + bn + row)) * IN_F + c16 * 8;
    }

    auto issue = [&](int slot, int kt) {
        const __nv_bfloat16* gk = g_XW + kt * BK;
        uint32_t sb = sbase + slot * STAGE_BYTES;
#pragma unroll
        for (int j = 0; j < 6; j++)
            asm volatile("cp.async.cg.shared.global [%0], [%1], 16;"
                         :: "r"(sb + s_off[j]), "l"(gk + g_off[j]));
    };

    float acc[4][8][4];
#pragma unroll
    for (int i = 0; i < 4; i++)
#pragma unroll
        for (int t = 0; t < 8; t++)
#pragma unroll
            for (int e = 0; e < 4; e++) acc[i][t][e] = 0.0f;

    // Prologue: fill 4 stages
#pragma unroll
    for (int s = 0; s < STAGES - 1; s++) {
        issue(s, s);
        asm volatile("cp.async.commit_group;\n");
    }

    const int r = lane & 15;     // ldmatrix row within 16
    const int c = lane >> 4;     // ldmatrix k-half (0/1)

    int slot = 0;
    for (int kt = 0; kt < NT; kt++) {
        asm volatile("cp.async.wait_group 3;\n");   // stage kt now resident
        __syncthreads();
        if (kt + STAGES - 1 < NT) {
            int ws = kt + STAGES - 1 - ((kt + STAGES - 1) / STAGES) * STAGES;
            issue(ws, kt + STAGES - 1);
        }
        asm volatile("cp.async.commit_group;\n");   // commit (possibly empty)

        const uint32_t sA = sbase + slot * STAGE_BYTES;
        const uint32_t sB = sA + A_BYTES;
#pragma unroll
        for (int ks = 0; ks < 2; ks++) {
            uint32_t a[4][4], b[4][4];
#pragma unroll
            for (int i = 0; i < 4; i++) {
                uint32_t addr = sA + (uint32_t)((wm + i * 16 + r) * LDSE + ks * 16 + c * 8) * 2;
                asm volatile("ldmatrix.sync.aligned.m8n8.x4.shared.b16 {%0,%1,%2,%3}, [%4];\n"
                    : "=r"(a[i][0]), "=r"(a[i][1]), "=r"(a[i][2]), "=r"(a[i][3]) : "r"(addr));
            }
#pragma unroll
            for (int j = 0; j < 4; j++) {
                uint32_t addr = sB + (uint32_t)((wn + j * 16 + r) * LDSE + ks * 16 + c * 8) * 2;
                asm volatile("ldmatrix.sync.aligned.m8n8.x4.shared.b16 {%0,%1,%2,%3}, [%4];\n"
                    : "=r"(b[j][0]), "=r"(b[j][1]), "=r"(b[j][2]), "=r"(b[j][3]) : "r"(addr));
            }
#pragma unroll
            for (int i = 0; i < 4; i++) {
#pragma unroll
                for (int t = 0; t < 8; t++) {
                    uint32_t bb0 = b[t >> 1][(t & 1)];
                    uint32_t bb1 = b[t >> 1][(t & 1) + 2];
                    asm volatile(
                        "mma.sync.aligned.m16n8k16.row.col.f32.bf16.bf16.f32 "
                        "{%0,%1,%2,%3}, {%4,%5,%6,%7}, {%8,%9}, {%0,%1,%2,%3};\n"
                        : "+f"(acc[i][t][0]), "+f"(acc[i][t][1]),
                          "+f"(acc[i][t][2]), "+f"(acc[i][t][3])
                        : "r"(a[i][0]), "r"(a[i][1]), "r"(a[i][2]), "r"(a[i][3]),
                          "r"(bb0), "r"(bb1));
                }
            }
        }
        if (++slot == STAGES) slot = 0;
    }

    // Epilogue: round through bf16 (reference result is bf16-valued), store fp32
#pragma unroll
    for (int i = 0; i < 4; i++) {
        int row0 = bm + wm + i * 16 + (lane >> 2);
#pragma unroll
        for (int t = 0; t < 8; t++) {
            int col = bn + wn + t * 8 + (lane & 3) * 2;
            float2 v0, v1;
            v0.x = __bfloat162float(__float2bfloat16(acc[i][t][0]));
            v0.y = __bfloat162float(__float2bfloat16(acc[i][t][1]));
            v1.x = __bfloat162float(__float2bfloat16(acc[i][t][2]));
            v1.y = __bfloat162float(__float2bfloat16(acc[i][t][3]));
            *reinterpret_cast<float2*>(C + (size_t)row0 * OUT_F + col)       = v0;
            *reinterpret_cast<float2*>(C + (size_t)(row0 + 8) * OUT_F + col) = v1;
        }
    }
}

// ---------------------------------------------------------------------------
// Launch: convert -> dequant -> GEMM (3 graph nodes, no allocs/syncs)
// ---------------------------------------------------------------------------
extern "C" void kernel_launch(void* const* d_in, const int* in_sizes, int n_in,
                              void* d_out, int out_size) {
    const float* x       = (const float*)d_in[0];
    const int*   qweight = (const int*)d_in[1];
    const int*   qzeros  = (const int*)d_in[2];
    const float* scales  = (const float*)d_in[3];
    float*       out     = (float*)d_out;

    cudaFuncSetAttribute(gemm_kernel,
                         cudaFuncAttributeMaxDynamicSharedMemorySize, DYN_SMEM);

    convert_x_kernel<<<16384, 256>>>(x);
    dequant_w_kernel<<<8192, 256>>>(qweight, qzeros, scales);
    dim3 grid(OUT_F / BN, M_TOT / BM);   // (16, 64) = 1024 CTAs
    gemm_kernel<<<grid, 256, DYN_SMEM>>>(out);
}

// round 10
// speedup vs baseline: 1.0943x; 1.0220x over previous
#include <cuda_runtime.h>
#include <cuda_bf16.h>
#include <cstdint>

// Problem constants
static constexpr int IN_F  = 4096;   // K
static constexpr int OUT_F = 4096;   // N
static constexpr int M_TOT = 8192;   // 4*2048

// GEMM tiling: CTA 128x256x32, 8 warps, warp tile 64x64, 5-stage cp.async ring
static constexpr int BM = 128, BN = 256, BK = 32;
static constexpr int STAGES = 5;
static constexpr int NT = IN_F / BK;                       // 128 K-stages
static constexpr int LDSE = 40;                            // 32 bf16 + 8 pad (80B row)
static constexpr int A_BYTES = BM * LDSE * 2;              // 10240
static constexpr int B_BYTES = BN * LDSE * 2;              // 20480
static constexpr int STAGE_BYTES = A_BYTES + B_BYTES;      // 30720
static constexpr int DYN_SMEM = STAGES * STAGE_BYTES;      // 153600

static constexpr int CONV_BLOCKS = (M_TOT * IN_F) / (256 * 8);   // 16384
static constexpr int DEQ_BLOCKS  = (IN_F / 8) * OUT_F / 256;     // 8192

// Fused scratch: X-bf16 rows [0, M_TOT), W-bf16 (B^T, [n][k]) rows [M_TOT, M_TOT+OUT_F)
__device__ __nv_bfloat16 g_XW[(size_t)(M_TOT + OUT_F) * IN_F];   // 96 MB

// ---------------------------------------------------------------------------
// Kernel 1 (fused prep): blocks [0,16384) convert x fp32->bf16;
// blocks [16384, 24576) dequant int4 W -> bf16 at rows [M_TOT, M_TOT+OUT_F).
// Both parts HBM-bound (convert measured at 77% of spec). scales are fp32
// (established R4/R5/R7 dtype experiments).
// ---------------------------------------------------------------------------
__global__ void prep_kernel(const float* __restrict__ x,
                            const int* __restrict__ qweight,
                            const int* __restrict__ qzeros,
                            const float* __restrict__ scales) {
    int b = blockIdx.x;
    if (b < CONV_BLOCKS) {
        size_t i = ((size_t)b * blockDim.x + threadIdx.x) * 8;
        float4 f0 = *reinterpret_cast<const float4*>(x + i);
        float4 f1 = *reinterpret_cast<const float4*>(x + i + 4);
        union { uint4 u; __nv_bfloat162 h[4]; } p;
        p.h[0] = __float22bfloat162_rn(make_float2(f0.x, f0.y));
        p.h[1] = __float22bfloat162_rn(make_float2(f0.z, f0.w));
        p.h[2] = __float22bfloat162_rn(make_float2(f1.x, f1.y));
        p.h[3] = __float22bfloat162_rn(make_float2(f1.z, f1.w));
        *reinterpret_cast<uint4*>(g_XW + i) = p.u;
    } else {
        int idx = (b - CONV_BLOCKS) * blockDim.x + threadIdx.x;   // 0 .. 512*4096-1
        int n = idx & (OUT_F - 1);
        int p = idx >> 12;
        int g = p >> 4;

        uint32_t w  = ((const uint32_t*)qweight)[idx];
        uint32_t zw = ((const uint32_t*)qzeros)[g * (OUT_F / 8) + (n >> 3)];
        float z = (float)((zw >> (4 * (n & 7))) & 15);
        float s = scales[g * OUT_F + n];

        union { uint4 u; __nv_bfloat16 h[8]; } outp;
#pragma unroll
        for (int j = 0; j < 8; j++) {
            float wv = (float)((w >> (4 * j)) & 15);
            outp.h[j] = __float2bfloat16((wv - z) * s);
        }
        *reinterpret_cast<uint4*>(g_XW + (size_t)(M_TOT + n) * IN_F + (size_t)p * 8) = outp.u;
    }
}

// ---------------------------------------------------------------------------
// Kernel 2: bf16 TN GEMM, HMMA path. Measured at ~95-100% of the legacy
// mma.sync ceiling (512 MACs/cyc/SM on sm_103; tcgen05 needs `a` features
// the harness toolchain rejects). 128x256 CTA tile, 64x64 warp tiles,
// 5-stage cp.async ring. Result rounded through bf16, stored fp32.
// ---------------------------------------------------------------------------
__global__ __launch_bounds__(256, 1)
void gemm_kernel(float* __restrict__ C) {
    extern __shared__ __align__(16) char smem[];

    const int tid  = threadIdx.x;
    const int lane = tid & 31;
    const int warp = tid >> 5;
    const int bm   = blockIdx.y * BM;
    const int bn   = blockIdx.x * BN;
    const int wm   = (warp & 1) * 64;    // warp row offset
    const int wn   = (warp >> 1) * 64;   // warp col offset

    const uint32_t sbase = (uint32_t)__cvta_generic_to_shared(smem);

    // cp.async mapping: 1536 16B chunks/stage (A:512, B:1024), 6 per thread
    uint32_t s_off[6];
    const __nv_bfloat16* gp[6];
#pragma unroll
    for (int j = 0; j < 6; j++) {
        int c    = tid + 256 * j;
        bool isA = c < 512;
        int cc   = isA ? c : c - 512;
        int row  = cc >> 2, c16 = cc & 3;
        s_off[j] = (isA ? 0u : (uint32_t)A_BYTES) + (uint32_t)(row * LDSE + c16 * 8) * 2;
        gp[j]    = g_XW + (size_t)(isA ? (bm + row) : (M_TOT + bn + row)) * IN_F + c16 * 8;
    }

    auto issue = [&](int slot) {
        uint32_t sb = sbase + slot * STAGE_BYTES;
#pragma unroll
        for (int j = 0; j < 6; j++) {
            asm volatile("cp.async.cg.shared.global [%0], [%1], 16;"
                         :: "r"(sb + s_off[j]), "l"(gp[j]));
            gp[j] += BK;   // advance K
        }
    };

    float acc[4][8][4];
#pragma unroll
    for (int i = 0; i < 4; i++)
#pragma unroll
        for (int t = 0; t < 8; t++)
#pragma unroll
            for (int e = 0; e < 4; e++) acc[i][t][e] = 0.0f;

    // Prologue: fill 4 stages
#pragma unroll
    for (int s = 0; s < STAGES - 1; s++) {
        issue(s);
        asm volatile("cp.async.commit_group;\n");
    }

    const int r = lane & 15;     // ldmatrix row within 16
    const int c = lane >> 4;     // ldmatrix k-half (0/1)

    // Precompute per-warp ldmatrix base offsets (stage-invariant part)
    uint32_t a_base[4], b_base[4];
#pragma unroll
    for (int i = 0; i < 4; i++)
        a_base[i] = (uint32_t)((wm + i * 16 + r) * LDSE + c * 8) * 2;
#pragma unroll
    for (int j = 0; j < 4; j++)
        b_base[j] = (uint32_t)A_BYTES + (uint32_t)((wn + j * 16 + r) * LDSE + c * 8) * 2;

    int slot = 0, wslot = STAGES - 1;
    for (int kt = 0; kt < NT; kt++) {
        asm volatile("cp.async.wait_group 3;\n");   // stage kt now resident
        __syncthreads();
        if (kt + STAGES - 1 < NT) issue(wslot);
        asm volatile("cp.async.commit_group;\n");   // commit (possibly empty)

        const uint32_t sS = sbase + slot * STAGE_BYTES;
#pragma unroll
        for (int ks = 0; ks < 2; ks++) {
            uint32_t a[4][4], b[4][4];
#pragma unroll
            for (int i = 0; i < 4; i++) {
                uint32_t addr = sS + a_base[i] + ks * 32;
                asm volatile("ldmatrix.sync.aligned.m8n8.x4.shared.b16 {%0,%1,%2,%3}, [%4];\n"
                    : "=r"(a[i][0]), "=r"(a[i][1]), "=r"(a[i][2]), "=r"(a[i][3]) : "r"(addr));
            }
#pragma unroll
            for (int j = 0; j < 4; j++) {
                uint32_t addr = sS + b_base[j] + ks * 32;
                asm volatile("ldmatrix.sync.aligned.m8n8.x4.shared.b16 {%0,%1,%2,%3}, [%4];\n"
                    : "=r"(b[j][0]), "=r"(b[j][1]), "=r"(b[j][2]), "=r"(b[j][3]) : "r"(addr));
            }
#pragma unroll
            for (int i = 0; i < 4; i++) {
#pragma unroll
                for (int t = 0; t < 8; t++) {
                    uint32_t bb0 = b[t >> 1][(t & 1)];
                    uint32_t bb1 = b[t >> 1][(t & 1) + 2];
                    asm volatile(
                        "mma.sync.aligned.m16n8k16.row.col.f32.bf16.bf16.f32 "
                        "{%0,%1,%2,%3}, {%4,%5,%6,%7}, {%8,%9}, {%0,%1,%2,%3};\n"
                        : "+f"(acc[i][t][0]), "+f"(acc[i][t][1]),
                          "+f"(acc[i][t][2]), "+f"(acc[i][t][3])
                        : "r"(a[i][0]), "r"(a[i][1]), "r"(a[i][2]), "r"(a[i][3]),
                          "r"(bb0), "r"(bb1));
                }
            }
        }
        if (++slot == STAGES) slot = 0;
        if (++wslot == STAGES) wslot = 0;
    }

    // Epilogue: round through bf16 (reference result is bf16-valued), store fp32
#pragma unroll
    for (int i = 0; i < 4; i++) {
        int row0 = bm + wm + i * 16 + (lane >> 2);
#pragma unroll
        for (int t = 0; t < 8; t++) {
            int col = bn + wn + t * 8 + (lane & 3) * 2;
            float2 v0, v1;
            v0.x = __bfloat162float(__float2bfloat16(acc[i][t][0]));
            v0.y = __bfloat162float(__float2bfloat16(acc[i][t][1]));
            v1.x = __bfloat162float(__float2bfloat16(acc[i][t][2]));
            v1.y = __bfloat162float(__float2bfloat16(acc[i][t][3]));
            *reinterpret_cast<float2*>(C + (size_t)row0 * OUT_F + col)       = v0;
            *reinterpret_cast<float2*>(C + (size_t)(row0 + 8) * OUT_F + col) = v1;
        }
    }
}

// ---------------------------------------------------------------------------
// Launch: fused prep -> GEMM (2 graph nodes, no allocs/syncs)
// ---------------------------------------------------------------------------
extern "C" void kernel_launch(void* const* d_in, const int* in_sizes, int n_in,
                              void* d_out, int out_size) {
    const float* x       = (const float*)d_in[0];
    const int*   qweight = (const int*)d_in[1];
    const int*   qzeros  = (const int*)d_in[2];
    const float* scales  = (const float*)d_in[3];
    float*       out     = (float*)d_out;

    cudaFuncSetAttribute(gemm_kernel,
                         cudaFuncAttributeMaxDynamicSharedMemorySize, DYN_SMEM);

    prep_kernel<<<CONV_BLOCKS + DEQ_BLOCKS, 256>>>(x, qweight, qzeros, scales);
    dim3 grid(OUT_F / BN, M_TOT / BM);   // (16, 64) = 1024 CTAs
    gemm_kernel<<<grid, 256, DYN_SMEM>>>(out);
}